// round 1
// baseline (speedup 1.0000x reference)
#include <cuda_runtime.h>
#include <cuda_bf16.h>
#include <math.h>

// ---------------------------------------------------------------------------
// Problem constants
// ---------------------------------------------------------------------------
#define BATCH   2
#define SEQ     2048
#define EMBED   1024
#define HEADS   16
#define DK      64
#define FFN     4096
#define MROWS   (BATCH * SEQ)          // 4096
#define LN_EPS  1e-5f

// ---------------------------------------------------------------------------
// Scratch buffers (allocation-free: __device__ globals)
// ---------------------------------------------------------------------------
__device__ float g_h [MROWS * EMBED];   // LN1 output
__device__ float g_q [MROWS * EMBED];
__device__ float g_k [MROWS * EMBED];
__device__ float g_v [MROWS * EMBED];
__device__ float g_ao[MROWS * EMBED];   // attention output (concat heads)
__device__ float g_x1[MROWS * EMBED];   // x + attn_out
__device__ float g_h2[MROWS * EMBED];   // LN2 output
__device__ float g_f [MROWS * FFN];     // relu(h2 @ W1^T + b1)

// ---------------------------------------------------------------------------
// LayerNorm: one block per row (N = 1024)
// ---------------------------------------------------------------------------
__global__ __launch_bounds__(256) void ln_kernel(
    const float* __restrict__ x, const float* __restrict__ g,
    const float* __restrict__ be, float* __restrict__ out)
{
    const int N = EMBED;
    const size_t row = blockIdx.x;
    const float* xr = x + row * N;
    float s = 0.f, s2 = 0.f;
    #pragma unroll
    for (int i = threadIdx.x; i < N; i += 256) {
        float v = xr[i];
        s += v; s2 += v * v;
    }
    #pragma unroll
    for (int o = 16; o; o >>= 1) {
        s  += __shfl_xor_sync(0xffffffffu, s,  o);
        s2 += __shfl_xor_sync(0xffffffffu, s2, o);
    }
    __shared__ float red[16];
    __shared__ float mu_sh, rs_sh;
    int w = threadIdx.x >> 5, l = threadIdx.x & 31;
    if (l == 0) { red[w] = s; red[8 + w] = s2; }
    __syncthreads();
    if (threadIdx.x == 0) {
        float ts = 0.f, ts2 = 0.f;
        #pragma unroll
        for (int i = 0; i < 8; i++) { ts += red[i]; ts2 += red[8 + i]; }
        float mu  = ts / N;
        float var = ts2 / N - mu * mu;
        mu_sh = mu;
        rs_sh = rsqrtf(var + LN_EPS);
    }
    __syncthreads();
    float mu = mu_sh, rs = rs_sh;
    float* outr = out + row * N;
    #pragma unroll
    for (int i = threadIdx.x; i < N; i += 256)
        outr[i] = (xr[i] - mu) * rs * g[i] + be[i];
}

// ---------------------------------------------------------------------------
// fp32 SGEMM:  C[M,N] = A[M,K] @ W[N,K]^T  (+bias, +relu, +residual)
// 128x128 tile, 8x8 per thread, K-step 16.
// EPI bit0 = relu, bit1 = residual add
// ---------------------------------------------------------------------------
template <int EPI>
__global__ __launch_bounds__(256) void gemm_kernel(
    const float* __restrict__ A, const float* __restrict__ W,
    const float* __restrict__ bias, const float* __restrict__ res,
    float* __restrict__ C, int M, int N, int K)
{
    const int TILE = 128, KT = 16;
    __shared__ float As[KT][TILE + 4];
    __shared__ float Bs[KT][TILE + 4];

    const int bm = blockIdx.y * TILE;
    const int bn = blockIdx.x * TILE;
    const int tid = threadIdx.x;
    const int tx = tid & 15;       // 0..15 (column group)
    const int ty = tid >> 4;       // 0..15 (row group)

    float acc[8][8];
    #pragma unroll
    for (int i = 0; i < 8; i++)
        #pragma unroll
        for (int j = 0; j < 8; j++) acc[i][j] = 0.f;

    for (int k0 = 0; k0 < K; k0 += KT) {
        // load A tile (128 rows x 16 cols) transposed into As[k][m]
        #pragma unroll
        for (int i = 0; i < 2; i++) {
            int idx = tid + i * 256;        // 0..511
            int row = idx >> 2;             // 0..127
            int c4  = idx & 3;              // float4 index within 16 cols
            float4 v = *(const float4*)&A[(size_t)(bm + row) * K + k0 + c4 * 4];
            As[c4 * 4 + 0][row] = v.x;
            As[c4 * 4 + 1][row] = v.y;
            As[c4 * 4 + 2][row] = v.z;
            As[c4 * 4 + 3][row] = v.w;
        }
        // load W tile (128 N-rows x 16 K-cols) transposed into Bs[k][n]
        #pragma unroll
        for (int i = 0; i < 2; i++) {
            int idx = tid + i * 256;
            int row = idx >> 2;
            int c4  = idx & 3;
            float4 v = *(const float4*)&W[(size_t)(bn + row) * K + k0 + c4 * 4];
            Bs[c4 * 4 + 0][row] = v.x;
            Bs[c4 * 4 + 1][row] = v.y;
            Bs[c4 * 4 + 2][row] = v.z;
            Bs[c4 * 4 + 3][row] = v.w;
        }
        __syncthreads();

        #pragma unroll
        for (int kk = 0; kk < KT; kk++) {
            float a[8], b[8];
            #pragma unroll
            for (int i = 0; i < 8; i++) a[i] = As[kk][ty + 16 * i];
            #pragma unroll
            for (int j = 0; j < 8; j++) b[j] = Bs[kk][tx + 16 * j];
            #pragma unroll
            for (int i = 0; i < 8; i++)
                #pragma unroll
                for (int j = 0; j < 8; j++)
                    acc[i][j] += a[i] * b[j];
        }
        __syncthreads();
    }

    #pragma unroll
    for (int i = 0; i < 8; i++) {
        int m = bm + ty + 16 * i;
        #pragma unroll
        for (int j = 0; j < 8; j++) {
            int n = bn + tx + 16 * j;
            float v = acc[i][j] + bias[n];
            if (EPI & 1) v = fmaxf(v, 0.f);
            if (EPI & 2) v += res[(size_t)m * N + n];
            C[(size_t)m * N + n] = v;
        }
    }
}

// ---------------------------------------------------------------------------
// Attention (flash-style, fp32).
// grid = (SEQ/128, HEADS, BATCH), block = 128 threads.
// Each thread owns one query row: q[64], o[64], p[64] register resident.
// K/V tiles (64x64) staged in shared.
// ---------------------------------------------------------------------------
__global__ __launch_bounds__(128) void attn_kernel(
    const float* __restrict__ Q, const float* __restrict__ K,
    const float* __restrict__ V, float* __restrict__ O)
{
    const int BQ = 128, BK = 64, D = DK;
    __shared__ float Ks[BK][D];
    __shared__ float Vs[BK][D];

    const int qb = blockIdx.x;
    const int h  = blockIdx.y;
    const int b  = blockIdx.z;
    const int tid = threadIdx.x;

    const size_t base = (size_t)b * SEQ * EMBED + (size_t)h * D; // + s*EMBED + d
    const int m0 = qb * BQ;
    const int r  = tid;     // this thread's query row within tile

    // load my q row into registers
    float q[D];
    {
        const float* qp = &Q[base + (size_t)(m0 + r) * EMBED];
        #pragma unroll
        for (int c = 0; c < D / 4; c++) {
            float4 v = *(const float4*)&qp[c * 4];
            q[c * 4 + 0] = v.x; q[c * 4 + 1] = v.y;
            q[c * 4 + 2] = v.z; q[c * 4 + 3] = v.w;
        }
    }

    float o[D];
    #pragma unroll
    for (int d = 0; d < D; d++) o[d] = 0.f;
    float mi = -1e30f, li = 0.f;

    for (int k0 = 0; k0 < SEQ; k0 += BK) {
        // cooperative load of K and V tiles (64x64 each)
        for (int i = tid; i < BK * (D / 4); i += 128) {
            int rr = i / (D / 4), c = i % (D / 4);
            *(float4*)&Ks[rr][c * 4] = *(const float4*)&K[base + (size_t)(k0 + rr) * EMBED + c * 4];
            *(float4*)&Vs[rr][c * 4] = *(const float4*)&V[base + (size_t)(k0 + rr) * EMBED + c * 4];
        }
        __syncthreads();

        float p[BK];
        float tmax = -1e30f;
        #pragma unroll 4
        for (int kk = 0; kk < BK; kk++) {
            float s = 0.f;
            #pragma unroll
            for (int d = 0; d < D; d++) s += q[d] * Ks[kk][d];
            s *= 0.125f;                    // 1/sqrt(64)
            p[kk] = s;
            tmax = fmaxf(tmax, s);
        }
        float mnew  = fmaxf(mi, tmax);
        float alpha = __expf(mi - mnew);
        float ps = 0.f;
        #pragma unroll 4
        for (int kk = 0; kk < BK; kk++) {
            p[kk] = __expf(p[kk] - mnew);
            ps += p[kk];
        }
        li = li * alpha + ps;
        #pragma unroll
        for (int d = 0; d < D; d++) {
            float accv = 0.f;
            #pragma unroll 4
            for (int kk = 0; kk < BK; kk++) accv += p[kk] * Vs[kk][d];
            o[d] = o[d] * alpha + accv;
        }
        mi = mnew;
        __syncthreads();
    }

    float inv = 1.f / li;
    float* op = &O[base + (size_t)(m0 + r) * EMBED];
    #pragma unroll
    for (int c = 0; c < D / 4; c++) {
        float4 v;
        v.x = o[c * 4 + 0] * inv; v.y = o[c * 4 + 1] * inv;
        v.z = o[c * 4 + 2] * inv; v.w = o[c * 4 + 3] * inv;
        *(float4*)&op[c * 4] = v;
    }
}

// ---------------------------------------------------------------------------
// Launch
// ---------------------------------------------------------------------------
extern "C" void kernel_launch(void* const* d_in, const int* in_sizes, int n_in,
                              void* d_out, int out_size)
{
    const float* x   = (const float*)d_in[0];
    const float* Wq  = (const float*)d_in[1];
    const float* bq  = (const float*)d_in[2];
    const float* Wk  = (const float*)d_in[3];
    const float* bk  = (const float*)d_in[4];
    const float* Wv  = (const float*)d_in[5];
    const float* bv  = (const float*)d_in[6];
    const float* Wo  = (const float*)d_in[7];
    const float* bo  = (const float*)d_in[8];
    const float* W1  = (const float*)d_in[9];
    const float* b1  = (const float*)d_in[10];
    const float* W2  = (const float*)d_in[11];
    const float* b2  = (const float*)d_in[12];
    const float* g1  = (const float*)d_in[13];
    const float* be1 = (const float*)d_in[14];
    const float* g2  = (const float*)d_in[15];
    const float* be2 = (const float*)d_in[16];
    float* out = (float*)d_out;

    float *h, *q, *k, *v, *ao, *x1, *h2, *f;
    cudaGetSymbolAddress((void**)&h,  g_h);
    cudaGetSymbolAddress((void**)&q,  g_q);
    cudaGetSymbolAddress((void**)&k,  g_k);
    cudaGetSymbolAddress((void**)&v,  g_v);
    cudaGetSymbolAddress((void**)&ao, g_ao);
    cudaGetSymbolAddress((void**)&x1, g_x1);
    cudaGetSymbolAddress((void**)&h2, g_h2);
    cudaGetSymbolAddress((void**)&f,  g_f);

    // LN1
    ln_kernel<<<MROWS, 256>>>(x, g1, be1, h);

    // Q, K, V projections (bias only)
    {
        dim3 grid(EMBED / 128, MROWS / 128);
        gemm_kernel<0><<<grid, 256>>>(h, Wq, bq, nullptr, q, MROWS, EMBED, EMBED);
        gemm_kernel<0><<<grid, 256>>>(h, Wk, bk, nullptr, k, MROWS, EMBED, EMBED);
        gemm_kernel<0><<<grid, 256>>>(h, Wv, bv, nullptr, v, MROWS, EMBED, EMBED);
    }

    // Attention
    {
        dim3 grid(SEQ / 128, HEADS, BATCH);
        attn_kernel<<<grid, 128>>>(q, k, v, ao);
    }

    // O projection + residual: x1 = x + ao @ Wo^T + bo
    {
        dim3 grid(EMBED / 128, MROWS / 128);
        gemm_kernel<2><<<grid, 256>>>(ao, Wo, bo, x, x1, MROWS, EMBED, EMBED);
    }

    // LN2
    ln_kernel<<<MROWS, 256>>>(x1, g2, be2, h2);

    // FFN1 + relu
    {
        dim3 grid(FFN / 128, MROWS / 128);
        gemm_kernel<1><<<grid, 256>>>(h2, W1, b1, nullptr, f, MROWS, FFN, EMBED);
    }

    // FFN2 + residual -> out
    {
        dim3 grid(EMBED / 128, MROWS / 128);
        gemm_kernel<2><<<grid, 256>>>(f, W2, b2, x1, out, MROWS, EMBED, FFN);
    }
}

// round 3
// speedup vs baseline: 3.1730x; 3.1730x over previous
#include <cuda_runtime.h>
#include <cuda_bf16.h>
#include <math.h>
#include <stdint.h>

// ---------------------------------------------------------------------------
// Problem constants
// ---------------------------------------------------------------------------
#define BATCH   2
#define SEQ     2048
#define EMBED   1024
#define HEADS   16
#define DK      64
#define FFN     4096
#define MROWS   (BATCH * SEQ)          // 4096
#define LN_EPS  1e-5f

// GEMM tiling
#define CTM 128
#define CTN 64
#define KTC 64
#define STAGE_BYTES 49152              // Ah 16K + Al 16K + Bh 8K + Bl 8K
#define SMEM_G (2 * STAGE_BYTES)       // 96 KB (double buffered)

#define SW128(o) ((o) ^ (((o) >> 3) & 0x70))

// ---------------------------------------------------------------------------
// Scratch buffers (allocation-free: __device__ globals)
// ---------------------------------------------------------------------------
__device__ __nv_bfloat16 g_h_hi [MROWS * EMBED];
__device__ __nv_bfloat16 g_h_lo [MROWS * EMBED];
__device__ float         g_q    [MROWS * EMBED];
__device__ float         g_k    [MROWS * EMBED];
__device__ float         g_v    [MROWS * EMBED];
__device__ __nv_bfloat16 g_ao_hi[MROWS * EMBED];
__device__ __nv_bfloat16 g_ao_lo[MROWS * EMBED];
__device__ float         g_x1   [MROWS * EMBED];
__device__ __nv_bfloat16 g_h2_hi[MROWS * EMBED];
__device__ __nv_bfloat16 g_h2_lo[MROWS * EMBED];
__device__ __nv_bfloat16 g_f_hi [MROWS * FFN];
__device__ __nv_bfloat16 g_f_lo [MROWS * FFN];

__device__ __nv_bfloat16 g_wq_hi[EMBED * EMBED];
__device__ __nv_bfloat16 g_wq_lo[EMBED * EMBED];
__device__ __nv_bfloat16 g_wk_hi[EMBED * EMBED];
__device__ __nv_bfloat16 g_wk_lo[EMBED * EMBED];
__device__ __nv_bfloat16 g_wv_hi[EMBED * EMBED];
__device__ __nv_bfloat16 g_wv_lo[EMBED * EMBED];
__device__ __nv_bfloat16 g_wo_hi[EMBED * EMBED];
__device__ __nv_bfloat16 g_wo_lo[EMBED * EMBED];
__device__ __nv_bfloat16 g_w1_hi[FFN * EMBED];
__device__ __nv_bfloat16 g_w1_lo[FFN * EMBED];
__device__ __nv_bfloat16 g_w2_hi[EMBED * FFN];
__device__ __nv_bfloat16 g_w2_lo[EMBED * FFN];

// ---------------------------------------------------------------------------
// helpers
// ---------------------------------------------------------------------------
static __device__ __forceinline__ uint32_t s2u(const void* p) {
    uint32_t a;
    asm("{ .reg .u64 t; cvta.to.shared.u64 t, %1; cvt.u32.u64 %0, t; }"
        : "=r"(a) : "l"(p));
    return a;
}
static __device__ __forceinline__ void cpa16(uint32_t s, const void* g) {
    asm volatile("cp.async.cg.shared.global [%0], [%1], 16;"
                 :: "r"(s), "l"(g) : "memory");
}
static __device__ __forceinline__ void ldsm4(uint32_t* f, uint32_t a) {
    asm volatile("ldmatrix.sync.aligned.m8n8.x4.shared.b16 {%0,%1,%2,%3}, [%4];"
                 : "=r"(f[0]), "=r"(f[1]), "=r"(f[2]), "=r"(f[3]) : "r"(a));
}
static __device__ __forceinline__ void mma16816(float* c, const uint32_t* a,
                                                uint32_t b0, uint32_t b1) {
    asm volatile(
        "mma.sync.aligned.m16n8k16.row.col.f32.bf16.bf16.f32 "
        "{%0,%1,%2,%3}, {%4,%5,%6,%7}, {%8,%9}, {%0,%1,%2,%3};"
        : "+f"(c[0]), "+f"(c[1]), "+f"(c[2]), "+f"(c[3])
        : "r"(a[0]), "r"(a[1]), "r"(a[2]), "r"(a[3]), "r"(b0), "r"(b1));
}
static __device__ __forceinline__ void split2(float v, __nv_bfloat16& h, __nv_bfloat16& l) {
    h = __float2bfloat16(v);
    l = __float2bfloat16(v - __bfloat162float(h));
}

// ---------------------------------------------------------------------------
// fp32 -> (hi, lo) bf16 conversion
// ---------------------------------------------------------------------------
__global__ __launch_bounds__(256) void cvt_kernel(
    const float* __restrict__ src, __nv_bfloat16* __restrict__ hi,
    __nv_bfloat16* __restrict__ lo, int n)
{
    int i = blockIdx.x * 256 + threadIdx.x;
    if (i < n) {
        __nv_bfloat16 h, l;
        split2(src[i], h, l);
        hi[i] = h; lo[i] = l;
    }
}

// ---------------------------------------------------------------------------
// LayerNorm: one block per row, writes (hi, lo) bf16
// ---------------------------------------------------------------------------
__global__ __launch_bounds__(256) void ln_kernel(
    const float* __restrict__ x, const float* __restrict__ g,
    const float* __restrict__ be, __nv_bfloat16* __restrict__ ohi,
    __nv_bfloat16* __restrict__ olo)
{
    const int N = EMBED;
    const size_t row = blockIdx.x;
    const float* xr = x + row * N;
    float s = 0.f, s2 = 0.f;
    #pragma unroll
    for (int i = threadIdx.x; i < N; i += 256) {
        float v = xr[i];
        s += v; s2 += v * v;
    }
    #pragma unroll
    for (int o = 16; o; o >>= 1) {
        s  += __shfl_xor_sync(0xffffffffu, s,  o);
        s2 += __shfl_xor_sync(0xffffffffu, s2, o);
    }
    __shared__ float red[16];
    __shared__ float mu_sh, rs_sh;
    int w = threadIdx.x >> 5, l = threadIdx.x & 31;
    if (l == 0) { red[w] = s; red[8 + w] = s2; }
    __syncthreads();
    if (threadIdx.x == 0) {
        float ts = 0.f, ts2 = 0.f;
        #pragma unroll
        for (int i = 0; i < 8; i++) { ts += red[i]; ts2 += red[8 + i]; }
        float mu  = ts / N;
        float var = ts2 / N - mu * mu;
        mu_sh = mu;
        rs_sh = rsqrtf(var + LN_EPS);
    }
    __syncthreads();
    float mu = mu_sh, rs = rs_sh;
    #pragma unroll
    for (int i = threadIdx.x; i < N; i += 256) {
        float y = (xr[i] - mu) * rs * g[i] + be[i];
        __nv_bfloat16 h, lo;
        split2(y, h, lo);
        ohi[row * N + i] = h;
        olo[row * N + i] = lo;
    }
}

// ---------------------------------------------------------------------------
// mma.sync split-bf16 GEMM:  C[M,N] = A[M,K] @ W[N,K]^T  (+bias,+relu,+res)
// A,W given as (hi, lo) bf16 pairs; C = Ah*Bh + Ah*Bl + Al*Bh, fp32 accum.
// CTA 128x64, K-chunk 64, double-buffered cp.async, 8 warps (4m x 2n),
// warp tile 32x32 (2 m16 x 4 n8 fragments).
// EPI: 0 = bias -> fp32; 2 = bias+res -> fp32; 5 = bias+relu -> (hi,lo) bf16
// ---------------------------------------------------------------------------
template <int EPI>
__global__ __launch_bounds__(256, 2) void gemm_mma(
    const __nv_bfloat16* __restrict__ Ah, const __nv_bfloat16* __restrict__ Al,
    const __nv_bfloat16* __restrict__ Bh, const __nv_bfloat16* __restrict__ Bl,
    const float* __restrict__ bias, const float* __restrict__ res,
    float* __restrict__ Cf, __nv_bfloat16* __restrict__ Chi,
    __nv_bfloat16* __restrict__ Clo, int M, int N, int K)
{
    extern __shared__ char smem[];
    const uint32_t sb = s2u(smem);
    const int tid = threadIdx.x;
    const int lane = tid & 31, w = tid >> 5;
    const int bm = blockIdx.y * CTM, bn = blockIdx.x * CTN;
    const int wm = (w & 3) * 32, wn = (w >> 2) * 32;

    float acc[2][4][4];
    #pragma unroll
    for (int mt = 0; mt < 2; mt++)
        #pragma unroll
        for (int nt = 0; nt < 4; nt++)
            #pragma unroll
            for (int i = 0; i < 4; i++) acc[mt][nt][i] = 0.f;

    const int NC = K / KTC;

    // ---- async load of one k-chunk into stage st ----
    auto load_chunk = [&](int c, int st) {
        const uint32_t s0 = sb + st * STAGE_BYTES;
        const size_t k0 = (size_t)c * KTC;
        #pragma unroll
        for (int i = 0; i < 4; i++) {                 // A: 128 rows x 128B
            int idx = i * 256 + tid;
            int row = idx >> 3, c16 = idx & 7;
            uint32_t so = SW128((uint32_t)(row * 128 + c16 * 16));
            const __nv_bfloat16* gh = Ah + (size_t)(bm + row) * K + k0 + c16 * 8;
            const __nv_bfloat16* gl = Al + (size_t)(bm + row) * K + k0 + c16 * 8;
            cpa16(s0 + so, gh);
            cpa16(s0 + 16384 + so, gl);
        }
        #pragma unroll
        for (int i = 0; i < 2; i++) {                 // B: 64 rows x 128B
            int idx = i * 256 + tid;
            int row = idx >> 3, c16 = idx & 7;
            uint32_t so = SW128((uint32_t)(row * 128 + c16 * 16));
            const __nv_bfloat16* gh = Bh + (size_t)(bn + row) * K + k0 + c16 * 8;
            const __nv_bfloat16* gl = Bl + (size_t)(bn + row) * K + k0 + c16 * 8;
            cpa16(s0 + 32768 + so, gh);
            cpa16(s0 + 40960 + so, gl);
        }
    };

    load_chunk(0, 0);
    asm volatile("cp.async.commit_group;" ::: "memory");

    for (int c = 0; c < NC; c++) {
        const int st = c & 1;
        if (c + 1 < NC) {
            load_chunk(c + 1, st ^ 1);
            asm volatile("cp.async.commit_group;" ::: "memory");
            asm volatile("cp.async.wait_group 1;" ::: "memory");
        } else {
            asm volatile("cp.async.wait_group 0;" ::: "memory");
        }
        __syncthreads();

        const uint32_t s0 = sb + st * STAGE_BYTES;
        #pragma unroll
        for (int ks = 0; ks < 4; ks++) {
            uint32_t ah[2][4], alr[2][4], bh[2][4], blr[2][4];
            const int arow = wm + (lane & 15);
            const int akb  = ks * 32 + (lane >> 4) * 16;
            #pragma unroll
            for (int mt = 0; mt < 2; mt++) {
                uint32_t ao = SW128((uint32_t)((arow + mt * 16) * 128 + akb));
                ldsm4(ah[mt],  s0 + ao);
                ldsm4(alr[mt], s0 + 16384 + ao);
            }
            const int brow = wn + ((lane >> 4) << 3) + (lane & 7);
            const int bkb  = ks * 32 + ((lane >> 3) & 1) * 16;
            #pragma unroll
            for (int np = 0; np < 2; np++) {
                uint32_t bo = SW128((uint32_t)((brow + np * 16) * 128 + bkb));
                ldsm4(bh[np],  s0 + 32768 + bo);
                ldsm4(blr[np], s0 + 40960 + bo);
            }
            #pragma unroll
            for (int mt = 0; mt < 2; mt++) {
                #pragma unroll
                for (int nt = 0; nt < 4; nt++) {
                    const int np = nt >> 1, ro = (nt & 1) * 2;
                    mma16816(acc[mt][nt], ah[mt],  bh[np][ro],  bh[np][ro + 1]);
                    mma16816(acc[mt][nt], ah[mt],  blr[np][ro], blr[np][ro + 1]);
                    mma16816(acc[mt][nt], alr[mt], bh[np][ro],  bh[np][ro + 1]);
                }
            }
        }
        __syncthreads();
    }

    // ---- epilogue ----
    #pragma unroll
    for (int mt = 0; mt < 2; mt++) {
        #pragma unroll
        for (int nt = 0; nt < 4; nt++) {
            const int n = bn + wn + nt * 8 + (lane & 3) * 2;
            const float bs0 = bias[n], bs1 = bias[n + 1];
            #pragma unroll
            for (int hh = 0; hh < 2; hh++) {
                const size_t m = (size_t)bm + wm + mt * 16 + (lane >> 2) + hh * 8;
                float v0 = acc[mt][nt][hh * 2]     + bs0;
                float v1 = acc[mt][nt][hh * 2 + 1] + bs1;
                if (EPI & 1) { v0 = fmaxf(v0, 0.f); v1 = fmaxf(v1, 0.f); }
                if (EPI & 2) {
                    float2 rr = *(const float2*)(res + m * N + n);
                    v0 += rr.x; v1 += rr.y;
                }
                if (EPI == 5) {
                    __nv_bfloat16 h0, l0, h1, l1;
                    split2(v0, h0, l0); split2(v1, h1, l1);
                    __nv_bfloat162 ph; ph.x = h0; ph.y = h1;
                    __nv_bfloat162 pl; pl.x = l0; pl.y = l1;
                    *(__nv_bfloat162*)(Chi + m * N + n) = ph;
                    *(__nv_bfloat162*)(Clo + m * N + n) = pl;
                } else {
                    float2 o; o.x = v0; o.y = v1;
                    *(float2*)(Cf + m * N + n) = o;
                }
            }
        }
    }
}

// ---------------------------------------------------------------------------
// Attention (flash-style, fp32, fully register-resident, BK=16 chunks).
// grid = (SEQ/128, HEADS, BATCH), block = 128 threads, 1 query row / thread.
// Writes (hi, lo) bf16 output for the O-projection GEMM.
// ---------------------------------------------------------------------------
__global__ __launch_bounds__(128) void attn_kernel(
    const float* __restrict__ Q, const float* __restrict__ K,
    const float* __restrict__ V, __nv_bfloat16* __restrict__ Ohi,
    __nv_bfloat16* __restrict__ Olo)
{
    __shared__ float4 Ks4[16][16];
    __shared__ float4 Vs4[16][16];

    const int qb = blockIdx.x;
    const int h  = blockIdx.y;
    const int b  = blockIdx.z;
    const int tid = threadIdx.x;

    const size_t base = (size_t)b * SEQ * EMBED + (size_t)h * DK;
    const int m0 = qb * 128;
    const int r  = tid;

    float4 qv[16];
    {
        const float4* qp = (const float4*)&Q[base + (size_t)(m0 + r) * EMBED];
        #pragma unroll
        for (int d4 = 0; d4 < 16; d4++) qv[d4] = qp[d4];
    }
    float4 ov[16];
    #pragma unroll
    for (int d4 = 0; d4 < 16; d4++) { ov[d4].x = 0.f; ov[d4].y = 0.f; ov[d4].z = 0.f; ov[d4].w = 0.f; }
    float mi = -1e30f, li = 0.f;

    for (int k0 = 0; k0 < SEQ; k0 += 16) {
        #pragma unroll
        for (int i = 0; i < 2; i++) {
            int idx = i * 128 + tid;
            int rr = idx >> 4, cc = idx & 15;
            Ks4[rr][cc] = *(const float4*)&K[base + (size_t)(k0 + rr) * EMBED + cc * 4];
            Vs4[rr][cc] = *(const float4*)&V[base + (size_t)(k0 + rr) * EMBED + cc * 4];
        }
        __syncthreads();

        float p[16];
        float tmax = -1e30f;
        #pragma unroll
        for (int kk = 0; kk < 16; kk++) {
            float s = 0.f;
            #pragma unroll
            for (int d4 = 0; d4 < 16; d4++) {
                float4 kv = Ks4[kk][d4];
                s += qv[d4].x * kv.x + qv[d4].y * kv.y
                   + qv[d4].z * kv.z + qv[d4].w * kv.w;
            }
            s *= 0.125f;
            p[kk] = s;
            tmax = fmaxf(tmax, s);
        }
        float mn = fmaxf(mi, tmax);
        float alpha = __expf(mi - mn);
        float ps = 0.f;
        #pragma unroll
        for (int kk = 0; kk < 16; kk++) {
            p[kk] = __expf(p[kk] - mn);
            ps += p[kk];
        }
        li = li * alpha + ps;
        #pragma unroll
        for (int d4 = 0; d4 < 16; d4++) {
            ov[d4].x *= alpha; ov[d4].y *= alpha;
            ov[d4].z *= alpha; ov[d4].w *= alpha;
        }
        #pragma unroll
        for (int kk = 0; kk < 16; kk++) {
            float pk = p[kk];
            #pragma unroll
            for (int d4 = 0; d4 < 16; d4++) {
                float4 vv = Vs4[kk][d4];
                ov[d4].x += pk * vv.x; ov[d4].y += pk * vv.y;
                ov[d4].z += pk * vv.z; ov[d4].w += pk * vv.w;
            }
        }
        mi = mn;
        __syncthreads();
    }

    const float inv = 1.f / li;
    const size_t ob = base + (size_t)(m0 + r) * EMBED;
    #pragma unroll
    for (int d4 = 0; d4 < 16; d4++) {
        float v0 = ov[d4].x * inv, v1 = ov[d4].y * inv;
        float v2 = ov[d4].z * inv, v3 = ov[d4].w * inv;
        __nv_bfloat16 h0, l0, h1, l1, h2, l2, h3, l3;
        split2(v0, h0, l0); split2(v1, h1, l1);
        split2(v2, h2, l2); split2(v3, h3, l3);
        __nv_bfloat162 a; a.x = h0; a.y = h1;
        __nv_bfloat162 bb; bb.x = h2; bb.y = h3;
        __nv_bfloat162 c; c.x = l0; c.y = l1;
        __nv_bfloat162 d; d.x = l2; d.y = l3;
        *(__nv_bfloat162*)(Ohi + ob + d4 * 4)     = a;
        *(__nv_bfloat162*)(Ohi + ob + d4 * 4 + 2) = bb;
        *(__nv_bfloat162*)(Olo + ob + d4 * 4)     = c;
        *(__nv_bfloat162*)(Olo + ob + d4 * 4 + 2) = d;
    }
}

// ---------------------------------------------------------------------------
// Launch
// ---------------------------------------------------------------------------
extern "C" void kernel_launch(void* const* d_in, const int* in_sizes, int n_in,
                              void* d_out, int out_size)
{
    const float* x   = (const float*)d_in[0];
    const float* Wq  = (const float*)d_in[1];
    const float* bq  = (const float*)d_in[2];
    const float* Wk  = (const float*)d_in[3];
    const float* bk  = (const float*)d_in[4];
    const float* Wv  = (const float*)d_in[5];
    const float* bv  = (const float*)d_in[6];
    const float* Wo  = (const float*)d_in[7];
    const float* bo  = (const float*)d_in[8];
    const float* W1  = (const float*)d_in[9];
    const float* b1  = (const float*)d_in[10];
    const float* W2  = (const float*)d_in[11];
    const float* b2  = (const float*)d_in[12];
    const float* g1  = (const float*)d_in[13];
    const float* be1 = (const float*)d_in[14];
    const float* g2  = (const float*)d_in[15];
    const float* be2 = (const float*)d_in[16];
    float* out = (float*)d_out;

    __nv_bfloat16 *h_hi, *h_lo, *ao_hi, *ao_lo, *h2_hi, *h2_lo, *f_hi, *f_lo;
    __nv_bfloat16 *wq_hi, *wq_lo, *wk_hi, *wk_lo, *wv_hi, *wv_lo, *wo_hi, *wo_lo;
    __nv_bfloat16 *w1_hi, *w1_lo, *w2_hi, *w2_lo;
    float *q, *k, *v, *x1;
    cudaGetSymbolAddress((void**)&h_hi,  g_h_hi);
    cudaGetSymbolAddress((void**)&h_lo,  g_h_lo);
    cudaGetSymbolAddress((void**)&q,     g_q);
    cudaGetSymbolAddress((void**)&k,     g_k);
    cudaGetSymbolAddress((void**)&v,     g_v);
    cudaGetSymbolAddress((void**)&ao_hi, g_ao_hi);
    cudaGetSymbolAddress((void**)&ao_lo, g_ao_lo);
    cudaGetSymbolAddress((void**)&x1,    g_x1);
    cudaGetSymbolAddress((void**)&h2_hi, g_h2_hi);
    cudaGetSymbolAddress((void**)&h2_lo, g_h2_lo);
    cudaGetSymbolAddress((void**)&f_hi,  g_f_hi);
    cudaGetSymbolAddress((void**)&f_lo,  g_f_lo);
    cudaGetSymbolAddress((void**)&wq_hi, g_wq_hi);
    cudaGetSymbolAddress((void**)&wq_lo, g_wq_lo);
    cudaGetSymbolAddress((void**)&wk_hi, g_wk_hi);
    cudaGetSymbolAddress((void**)&wk_lo, g_wk_lo);
    cudaGetSymbolAddress((void**)&wv_hi, g_wv_hi);
    cudaGetSymbolAddress((void**)&wv_lo, g_wv_lo);
    cudaGetSymbolAddress((void**)&wo_hi, g_wo_hi);
    cudaGetSymbolAddress((void**)&wo_lo, g_wo_lo);
    cudaGetSymbolAddress((void**)&w1_hi, g_w1_hi);
    cudaGetSymbolAddress((void**)&w1_lo, g_w1_lo);
    cudaGetSymbolAddress((void**)&w2_hi, g_w2_hi);
    cudaGetSymbolAddress((void**)&w2_lo, g_w2_lo);

    cudaFuncSetAttribute(gemm_mma<0>, cudaFuncAttributeMaxDynamicSharedMemorySize, SMEM_G);
    cudaFuncSetAttribute(gemm_mma<2>, cudaFuncAttributeMaxDynamicSharedMemorySize, SMEM_G);
    cudaFuncSetAttribute(gemm_mma<5>, cudaFuncAttributeMaxDynamicSharedMemorySize, SMEM_G);

    const int NE = EMBED * EMBED;      // 1M
    const int NF = FFN * EMBED;        // 4M
    cvt_kernel<<<NE / 256, 256>>>(Wq, wq_hi, wq_lo, NE);
    cvt_kernel<<<NE / 256, 256>>>(Wk, wk_hi, wk_lo, NE);
    cvt_kernel<<<NE / 256, 256>>>(Wv, wv_hi, wv_lo, NE);
    cvt_kernel<<<NE / 256, 256>>>(Wo, wo_hi, wo_lo, NE);
    cvt_kernel<<<NF / 256, 256>>>(W1, w1_hi, w1_lo, NF);
    cvt_kernel<<<NF / 256, 256>>>(W2, w2_hi, w2_lo, NF);

    // LN1 -> (hi, lo)
    ln_kernel<<<MROWS, 256>>>(x, g1, be1, h_hi, h_lo);

    // Q, K, V projections (bias, fp32 out)
    {
        dim3 grid(EMBED / CTN, MROWS / CTM);
        gemm_mma<0><<<grid, 256, SMEM_G>>>(h_hi, h_lo, wq_hi, wq_lo, bq, nullptr,
                                           q, nullptr, nullptr, MROWS, EMBED, EMBED);
        gemm_mma<0><<<grid, 256, SMEM_G>>>(h_hi, h_lo, wk_hi, wk_lo, bk, nullptr,
                                           k, nullptr, nullptr, MROWS, EMBED, EMBED);
        gemm_mma<0><<<grid, 256, SMEM_G>>>(h_hi, h_lo, wv_hi, wv_lo, bv, nullptr,
                                           v, nullptr, nullptr, MROWS, EMBED, EMBED);
    }

    // Attention -> ao (hi, lo)
    {
        dim3 grid(SEQ / 128, HEADS, BATCH);
        attn_kernel<<<grid, 128>>>(q, k, v, ao_hi, ao_lo);
    }

    // O projection + residual: x1 = x + ao @ Wo^T + bo
    {
        dim3 grid(EMBED / CTN, MROWS / CTM);
        gemm_mma<2><<<grid, 256, SMEM_G>>>(ao_hi, ao_lo, wo_hi, wo_lo, bo, x,
                                           x1, nullptr, nullptr, MROWS, EMBED, EMBED);
    }

    // LN2 -> (hi, lo)
    ln_kernel<<<MROWS, 256>>>(x1, g2, be2, h2_hi, h2_lo);

    // FFN1 + relu -> f (hi, lo)
    {
        dim3 grid(FFN / CTN, MROWS / CTM);
        gemm_mma<5><<<grid, 256, SMEM_G>>>(h2_hi, h2_lo, w1_hi, w1_lo, b1, nullptr,
                                           nullptr, f_hi, f_lo, MROWS, FFN, EMBED);
    }

    // FFN2 + residual -> out
    {
        dim3 grid(EMBED / CTN, MROWS / CTM);
        gemm_mma<2><<<grid, 256, SMEM_G>>>(f_hi, f_lo, w2_hi, w2_lo, b2, x1,
                                           out, nullptr, nullptr, MROWS, EMBED, FFN);
    }
}

// round 4
// speedup vs baseline: 5.7649x; 1.8169x over previous
#include <cuda_runtime.h>
#include <cuda_bf16.h>
#include <math.h>
#include <stdint.h>

// ---------------------------------------------------------------------------
// Problem constants
// ---------------------------------------------------------------------------
#define BATCH   2
#define SEQ     2048
#define EMBED   1024
#define HEADS   16
#define DK      64
#define FFN     4096
#define MROWS   (BATCH * SEQ)          // 4096
#define LN_EPS  1e-5f
#define SSC     0.1803368801111204f    // 0.125 * log2(e)

// GEMM tiling
#define CTM 128
#define CTN 64
#define KTC 64
#define STAGE_BYTES 49152              // Ah 16K + Al 16K + Bh 8K + Bl 8K
#define SMEM_G (2 * STAGE_BYTES)       // 96 KB (double buffered)

// Attention smem: Qh 16K + Ql 16K + 2 stages * (Kh+Kl+Vh+Vl = 32K)
#define SMEM_A (32768 + 2 * 32768)     // 96 KB

#define SW128(o) ((o) ^ (((o) >> 3) & 0x70))

// ---------------------------------------------------------------------------
// Scratch buffers (allocation-free: __device__ globals)
// ---------------------------------------------------------------------------
__device__ __nv_bfloat16 g_h_hi [MROWS * EMBED];
__device__ __nv_bfloat16 g_h_lo [MROWS * EMBED];
__device__ __nv_bfloat16 g_q_hi [MROWS * EMBED];   // [B,H,S,DK]
__device__ __nv_bfloat16 g_q_lo [MROWS * EMBED];
__device__ __nv_bfloat16 g_k_hi [MROWS * EMBED];
__device__ __nv_bfloat16 g_k_lo [MROWS * EMBED];
__device__ __nv_bfloat16 g_v_hi [MROWS * EMBED];
__device__ __nv_bfloat16 g_v_lo [MROWS * EMBED];
__device__ __nv_bfloat16 g_ao_hi[MROWS * EMBED];
__device__ __nv_bfloat16 g_ao_lo[MROWS * EMBED];
__device__ float         g_x1   [MROWS * EMBED];
__device__ __nv_bfloat16 g_h2_hi[MROWS * EMBED];
__device__ __nv_bfloat16 g_h2_lo[MROWS * EMBED];
__device__ __nv_bfloat16 g_f_hi [MROWS * FFN];
__device__ __nv_bfloat16 g_f_lo [MROWS * FFN];

__device__ __nv_bfloat16 g_wq_hi[EMBED * EMBED];
__device__ __nv_bfloat16 g_wq_lo[EMBED * EMBED];
__device__ __nv_bfloat16 g_wk_hi[EMBED * EMBED];
__device__ __nv_bfloat16 g_wk_lo[EMBED * EMBED];
__device__ __nv_bfloat16 g_wv_hi[EMBED * EMBED];
__device__ __nv_bfloat16 g_wv_lo[EMBED * EMBED];
__device__ __nv_bfloat16 g_wo_hi[EMBED * EMBED];
__device__ __nv_bfloat16 g_wo_lo[EMBED * EMBED];
__device__ __nv_bfloat16 g_w1_hi[FFN * EMBED];
__device__ __nv_bfloat16 g_w1_lo[FFN * EMBED];
__device__ __nv_bfloat16 g_w2_hi[EMBED * FFN];
__device__ __nv_bfloat16 g_w2_lo[EMBED * FFN];

// ---------------------------------------------------------------------------
// helpers
// ---------------------------------------------------------------------------
static __device__ __forceinline__ uint32_t s2u(const void* p) {
    uint32_t a;
    asm("{ .reg .u64 t; cvta.to.shared.u64 t, %1; cvt.u32.u64 %0, t; }"
        : "=r"(a) : "l"(p));
    return a;
}
static __device__ __forceinline__ void cpa16(uint32_t s, const void* g) {
    asm volatile("cp.async.cg.shared.global [%0], [%1], 16;"
                 :: "r"(s), "l"(g) : "memory");
}
static __device__ __forceinline__ void ldsm4(uint32_t* f, uint32_t a) {
    asm volatile("ldmatrix.sync.aligned.m8n8.x4.shared.b16 {%0,%1,%2,%3}, [%4];"
                 : "=r"(f[0]), "=r"(f[1]), "=r"(f[2]), "=r"(f[3]) : "r"(a));
}
static __device__ __forceinline__ void ldsm4t(uint32_t* f, uint32_t a) {
    asm volatile("ldmatrix.sync.aligned.m8n8.x4.trans.shared.b16 {%0,%1,%2,%3}, [%4];"
                 : "=r"(f[0]), "=r"(f[1]), "=r"(f[2]), "=r"(f[3]) : "r"(a));
}
static __device__ __forceinline__ void mma16816(float* c, const uint32_t* a,
                                                uint32_t b0, uint32_t b1) {
    asm volatile(
        "mma.sync.aligned.m16n8k16.row.col.f32.bf16.bf16.f32 "
        "{%0,%1,%2,%3}, {%4,%5,%6,%7}, {%8,%9}, {%0,%1,%2,%3};"
        : "+f"(c[0]), "+f"(c[1]), "+f"(c[2]), "+f"(c[3])
        : "r"(a[0]), "r"(a[1]), "r"(a[2]), "r"(a[3]), "r"(b0), "r"(b1));
}
static __device__ __forceinline__ float ex2f(float x) {
    float y;
    asm("ex2.approx.f32 %0, %1;" : "=f"(y) : "f"(x));
    return y;
}
static __device__ __forceinline__ void split2(float v, __nv_bfloat16& h, __nv_bfloat16& l) {
    h = __float2bfloat16(v);
    l = __float2bfloat16(v - __bfloat162float(h));
}
static __device__ __forceinline__ void pack_hl(float x, float y,
                                               uint32_t& hi, uint32_t& lo) {
    __nv_bfloat16 hx, lx, hy, ly;
    split2(x, hx, lx);
    split2(y, hy, ly);
    __nv_bfloat162 H; H.x = hx; H.y = hy;
    __nv_bfloat162 L; L.x = lx; L.y = ly;
    hi = *(uint32_t*)&H;
    lo = *(uint32_t*)&L;
}

// ---------------------------------------------------------------------------
// fp32 -> (hi, lo) bf16 conversion (vectorized, n % 4 == 0)
// ---------------------------------------------------------------------------
__global__ __launch_bounds__(256) void cvt_kernel(
    const float* __restrict__ src, __nv_bfloat16* __restrict__ hi,
    __nv_bfloat16* __restrict__ lo, int n4)
{
    int i = blockIdx.x * 256 + threadIdx.x;
    if (i < n4) {
        float4 v = ((const float4*)src)[i];
        uint32_t h0, l0, h1, l1;
        pack_hl(v.x, v.y, h0, l0);
        pack_hl(v.z, v.w, h1, l1);
        uint2 H; H.x = h0; H.y = h1;
        uint2 L; L.x = l0; L.y = l1;
        ((uint2*)hi)[i] = H;
        ((uint2*)lo)[i] = L;
    }
}

// ---------------------------------------------------------------------------
// LayerNorm: one block per row, writes (hi, lo) bf16
// ---------------------------------------------------------------------------
__global__ __launch_bounds__(256) void ln_kernel(
    const float* __restrict__ x, const float* __restrict__ g,
    const float* __restrict__ be, __nv_bfloat16* __restrict__ ohi,
    __nv_bfloat16* __restrict__ olo)
{
    const int N = EMBED;
    const size_t row = blockIdx.x;
    const float* xr = x + row * N;
    float s = 0.f, s2 = 0.f;
    #pragma unroll
    for (int i = threadIdx.x; i < N; i += 256) {
        float v = xr[i];
        s += v; s2 += v * v;
    }
    #pragma unroll
    for (int o = 16; o; o >>= 1) {
        s  += __shfl_xor_sync(0xffffffffu, s,  o);
        s2 += __shfl_xor_sync(0xffffffffu, s2, o);
    }
    __shared__ float red[16];
    __shared__ float mu_sh, rs_sh;
    int w = threadIdx.x >> 5, l = threadIdx.x & 31;
    if (l == 0) { red[w] = s; red[8 + w] = s2; }
    __syncthreads();
    if (threadIdx.x == 0) {
        float ts = 0.f, ts2 = 0.f;
        #pragma unroll
        for (int i = 0; i < 8; i++) { ts += red[i]; ts2 += red[8 + i]; }
        float mu  = ts / N;
        float var = ts2 / N - mu * mu;
        mu_sh = mu;
        rs_sh = rsqrtf(var + LN_EPS);
    }
    __syncthreads();
    float mu = mu_sh, rs = rs_sh;
    #pragma unroll
    for (int i = threadIdx.x; i < N; i += 256) {
        float y = (xr[i] - mu) * rs * g[i] + be[i];
        __nv_bfloat16 h, lo;
        split2(y, h, lo);
        ohi[row * N + i] = h;
        olo[row * N + i] = lo;
    }
}

// ---------------------------------------------------------------------------
// mma.sync split-bf16 GEMM:  C[M,N] = A[M,K] @ W[N,K]^T  (+bias,+relu,+res)
// EPI: 0 = bias -> fp32; 2 = bias+res -> fp32; 5 = bias+relu -> (hi,lo);
//      6 = bias -> (hi,lo) in head layout [B,H,S,DK]
// ---------------------------------------------------------------------------
template <int EPI>
__global__ __launch_bounds__(256, 2) void gemm_mma(
    const __nv_bfloat16* __restrict__ Ah, const __nv_bfloat16* __restrict__ Al,
    const __nv_bfloat16* __restrict__ Bh, const __nv_bfloat16* __restrict__ Bl,
    const float* __restrict__ bias, const float* __restrict__ res,
    float* __restrict__ Cf, __nv_bfloat16* __restrict__ Chi,
    __nv_bfloat16* __restrict__ Clo, int M, int N, int K)
{
    extern __shared__ char smem[];
    const uint32_t sb = s2u(smem);
    const int tid = threadIdx.x;
    const int lane = tid & 31, w = tid >> 5;
    const int bm = blockIdx.y * CTM, bn = blockIdx.x * CTN;
    const int wm = (w & 3) * 32, wn = (w >> 2) * 32;

    float acc[2][4][4];
    #pragma unroll
    for (int mt = 0; mt < 2; mt++)
        #pragma unroll
        for (int nt = 0; nt < 4; nt++)
            #pragma unroll
            for (int i = 0; i < 4; i++) acc[mt][nt][i] = 0.f;

    const int NC = K / KTC;

    auto load_chunk = [&](int c, int st) {
        const uint32_t s0 = sb + st * STAGE_BYTES;
        const size_t k0 = (size_t)c * KTC;
        #pragma unroll
        for (int i = 0; i < 4; i++) {                 // A: 128 rows x 128B
            int idx = i * 256 + tid;
            int row = idx >> 3, c16 = idx & 7;
            uint32_t so = SW128((uint32_t)(row * 128 + c16 * 16));
            const __nv_bfloat16* gh = Ah + (size_t)(bm + row) * K + k0 + c16 * 8;
            const __nv_bfloat16* gl = Al + (size_t)(bm + row) * K + k0 + c16 * 8;
            cpa16(s0 + so, gh);
            cpa16(s0 + 16384 + so, gl);
        }
        #pragma unroll
        for (int i = 0; i < 2; i++) {                 // B: 64 rows x 128B
            int idx = i * 256 + tid;
            int row = idx >> 3, c16 = idx & 7;
            uint32_t so = SW128((uint32_t)(row * 128 + c16 * 16));
            const __nv_bfloat16* gh = Bh + (size_t)(bn + row) * K + k0 + c16 * 8;
            const __nv_bfloat16* gl = Bl + (size_t)(bn + row) * K + k0 + c16 * 8;
            cpa16(s0 + 32768 + so, gh);
            cpa16(s0 + 40960 + so, gl);
        }
    };

    load_chunk(0, 0);
    asm volatile("cp.async.commit_group;" ::: "memory");

    for (int c = 0; c < NC; c++) {
        const int st = c & 1;
        if (c + 1 < NC) {
            load_chunk(c + 1, st ^ 1);
            asm volatile("cp.async.commit_group;" ::: "memory");
            asm volatile("cp.async.wait_group 1;" ::: "memory");
        } else {
            asm volatile("cp.async.wait_group 0;" ::: "memory");
        }
        __syncthreads();

        const uint32_t s0 = sb + st * STAGE_BYTES;
        #pragma unroll
        for (int ks = 0; ks < 4; ks++) {
            uint32_t ah[2][4], alr[2][4], bh[2][4], blr[2][4];
            const int arow = wm + (lane & 15);
            const int akb  = ks * 32 + (lane >> 4) * 16;
            #pragma unroll
            for (int mt = 0; mt < 2; mt++) {
                uint32_t ao = SW128((uint32_t)((arow + mt * 16) * 128 + akb));
                ldsm4(ah[mt],  s0 + ao);
                ldsm4(alr[mt], s0 + 16384 + ao);
            }
            const int brow = wn + ((lane >> 4) << 3) + (lane & 7);
            const int bkb  = ks * 32 + ((lane >> 3) & 1) * 16;
            #pragma unroll
            for (int np = 0; np < 2; np++) {
                uint32_t bo = SW128((uint32_t)((brow + np * 16) * 128 + bkb));
                ldsm4(bh[np],  s0 + 32768 + bo);
                ldsm4(blr[np], s0 + 40960 + bo);
            }
            #pragma unroll
            for (int mt = 0; mt < 2; mt++) {
                #pragma unroll
                for (int nt = 0; nt < 4; nt++) {
                    const int np = nt >> 1, ro = (nt & 1) * 2;
                    mma16816(acc[mt][nt], ah[mt],  bh[np][ro],  bh[np][ro + 1]);
                    mma16816(acc[mt][nt], ah[mt],  blr[np][ro], blr[np][ro + 1]);
                    mma16816(acc[mt][nt], alr[mt], bh[np][ro],  bh[np][ro + 1]);
                }
            }
        }
        __syncthreads();
    }

    // ---- epilogue ----
    #pragma unroll
    for (int mt = 0; mt < 2; mt++) {
        #pragma unroll
        for (int nt = 0; nt < 4; nt++) {
            const int n = bn + wn + nt * 8 + (lane & 3) * 2;
            const float bs0 = bias[n], bs1 = bias[n + 1];
            #pragma unroll
            for (int hh = 0; hh < 2; hh++) {
                const size_t m = (size_t)bm + wm + mt * 16 + (lane >> 2) + hh * 8;
                float v0 = acc[mt][nt][hh * 2]     + bs0;
                float v1 = acc[mt][nt][hh * 2 + 1] + bs1;
                if (EPI == 5) { v0 = fmaxf(v0, 0.f); v1 = fmaxf(v1, 0.f); }
                if (EPI == 2) {
                    float2 rr = *(const float2*)(res + m * N + n);
                    v0 += rr.x; v1 += rr.y;
                }
                if (EPI == 5) {
                    uint32_t ph, pl;
                    pack_hl(v0, v1, ph, pl);
                    *(uint32_t*)(Chi + m * N + n) = ph;
                    *(uint32_t*)(Clo + m * N + n) = pl;
                } else if (EPI == 6) {
                    // head layout: dst = ((b*H + h)*SEQ + s)*DK + d
                    const int b_ = (int)(m >> 11), s_ = (int)(m & 2047);
                    const int h_ = n >> 6, d_ = n & 63;
                    const size_t di = (((size_t)b_ * HEADS + h_) * SEQ + s_) * DK + d_;
                    uint32_t ph, pl;
                    pack_hl(v0, v1, ph, pl);
                    *(uint32_t*)(Chi + di) = ph;
                    *(uint32_t*)(Clo + di) = pl;
                } else {
                    float2 o; o.x = v0; o.y = v1;
                    *(float2*)(Cf + m * N + n) = o;
                }
            }
        }
    }
}

// ---------------------------------------------------------------------------
// Flash attention on tensor cores (split bf16, mma.sync).
// grid = (SEQ/128, HEADS, BATCH), 256 threads (8 warps, each owns 16 q rows).
// Q/K/V in [B,H,S,DK] (hi,lo) bf16. Output -> ao (hi,lo) in [B,S,E].
// ---------------------------------------------------------------------------
__global__ __launch_bounds__(256) void attn_mma(
    const __nv_bfloat16* __restrict__ Qh, const __nv_bfloat16* __restrict__ Ql,
    const __nv_bfloat16* __restrict__ Kh, const __nv_bfloat16* __restrict__ Kl,
    const __nv_bfloat16* __restrict__ Vh, const __nv_bfloat16* __restrict__ Vl,
    __nv_bfloat16* __restrict__ Ohi, __nv_bfloat16* __restrict__ Olo)
{
    extern __shared__ char smem[];
    const uint32_t sb  = s2u(smem);
    const uint32_t sQh = sb, sQl = sb + 16384;
    const int tid = threadIdx.x, lane = tid & 31, w = tid >> 5;
    const int qt = blockIdx.x, hd = blockIdx.y, b = blockIdx.z;
    const size_t hb = ((size_t)b * HEADS + hd) * SEQ * DK;
    const int m0 = qt * 128;
    const int wm = w * 16;

    // Q loads (one-time)
    #pragma unroll
    for (int i = 0; i < 4; i++) {
        int idx = i * 256 + tid;
        int row = idx >> 3, c16 = idx & 7;
        uint32_t so = SW128((uint32_t)(row * 128 + c16 * 16));
        const size_t g = hb + (size_t)(m0 + row) * DK + c16 * 8;
        cpa16(sQh + so, Qh + g);
        cpa16(sQl + so, Ql + g);
    }
    auto load_kv = [&](int c, int st) {
        const uint32_t s0 = sb + 32768 + st * 32768;
        const int k0 = c * 64;
        #pragma unroll
        for (int i = 0; i < 2; i++) {
            int idx = i * 256 + tid;
            int row = idx >> 3, c16 = idx & 7;
            uint32_t so = SW128((uint32_t)(row * 128 + c16 * 16));
            const size_t g = hb + (size_t)(k0 + row) * DK + c16 * 8;
            cpa16(s0 + so,         Kh + g);
            cpa16(s0 + 8192 + so,  Kl + g);
            cpa16(s0 + 16384 + so, Vh + g);
            cpa16(s0 + 24576 + so, Vl + g);
        }
    };
    load_kv(0, 0);
    asm volatile("cp.async.commit_group;" ::: "memory");

    uint32_t qhf[4][4], qlf[4][4];
    float o[8][4];
    #pragma unroll
    for (int j = 0; j < 8; j++)
        #pragma unroll
        for (int i = 0; i < 4; i++) o[j][i] = 0.f;
    float mr0 = -1e30f, mr1 = -1e30f, l0 = 0.f, l1 = 0.f;

    const int NC = SEQ / 64;
    for (int c = 0; c < NC; c++) {
        const int st = c & 1;
        if (c + 1 < NC) {
            load_kv(c + 1, st ^ 1);
            asm volatile("cp.async.commit_group;" ::: "memory");
            asm volatile("cp.async.wait_group 1;" ::: "memory");
        } else {
            asm volatile("cp.async.wait_group 0;" ::: "memory");
        }
        __syncthreads();

        if (c == 0) {
            #pragma unroll
            for (int ks = 0; ks < 4; ks++) {
                uint32_t ao = SW128((uint32_t)((wm + (lane & 15)) * 128
                                               + ks * 32 + (lane >> 4) * 16));
                ldsm4(qhf[ks], sQh + ao);
                ldsm4(qlf[ks], sQl + ao);
            }
        }
        const uint32_t s0 = sb + 32768 + st * 32768;

        // ---- S = Q K^T ----
        float sacc[8][4];
        #pragma unroll
        for (int j = 0; j < 8; j++)
            #pragma unroll
            for (int i = 0; i < 4; i++) sacc[j][i] = 0.f;

        #pragma unroll
        for (int ks = 0; ks < 4; ks++) {
            const int brow = ((lane >> 4) << 3) + (lane & 7);
            const int bkb  = ks * 32 + ((lane >> 3) & 1) * 16;
            #pragma unroll
            for (int np = 0; np < 4; np++) {
                uint32_t kh[4], kl[4];
                uint32_t bo = SW128((uint32_t)((brow + np * 16) * 128 + bkb));
                ldsm4(kh, s0 + bo);
                ldsm4(kl, s0 + 8192 + bo);
                mma16816(sacc[np * 2],     qhf[ks], kh[0], kh[1]);
                mma16816(sacc[np * 2],     qhf[ks], kl[0], kl[1]);
                mma16816(sacc[np * 2],     qlf[ks], kh[0], kh[1]);
                mma16816(sacc[np * 2 + 1], qhf[ks], kh[2], kh[3]);
                mma16816(sacc[np * 2 + 1], qhf[ks], kl[2], kl[3]);
                mma16816(sacc[np * 2 + 1], qlf[ks], kh[2], kh[3]);
            }
        }

        // ---- online softmax ----
        float cm0 = -1e30f, cm1 = -1e30f;
        #pragma unroll
        for (int j = 0; j < 8; j++) {
            cm0 = fmaxf(cm0, fmaxf(sacc[j][0], sacc[j][1]));
            cm1 = fmaxf(cm1, fmaxf(sacc[j][2], sacc[j][3]));
        }
        #pragma unroll
        for (int off = 1; off <= 2; off <<= 1) {
            cm0 = fmaxf(cm0, __shfl_xor_sync(0xffffffffu, cm0, off));
            cm1 = fmaxf(cm1, __shfl_xor_sync(0xffffffffu, cm1, off));
        }
        const float mn0 = fmaxf(mr0, cm0), mn1 = fmaxf(mr1, cm1);
        const float a0 = ex2f((mr0 - mn0) * SSC);
        const float a1 = ex2f((mr1 - mn1) * SSC);
        mr0 = mn0; mr1 = mn1;
        float sum0 = 0.f, sum1 = 0.f;
        #pragma unroll
        for (int j = 0; j < 8; j++) {
            sacc[j][0] = ex2f((sacc[j][0] - mn0) * SSC);
            sacc[j][1] = ex2f((sacc[j][1] - mn0) * SSC);
            sacc[j][2] = ex2f((sacc[j][2] - mn1) * SSC);
            sacc[j][3] = ex2f((sacc[j][3] - mn1) * SSC);
            sum0 += sacc[j][0] + sacc[j][1];
            sum1 += sacc[j][2] + sacc[j][3];
        }
        #pragma unroll
        for (int off = 1; off <= 2; off <<= 1) {
            sum0 += __shfl_xor_sync(0xffffffffu, sum0, off);
            sum1 += __shfl_xor_sync(0xffffffffu, sum1, off);
        }
        l0 = l0 * a0 + sum0;
        l1 = l1 * a1 + sum1;
        #pragma unroll
        for (int j = 0; j < 8; j++) {
            o[j][0] *= a0; o[j][1] *= a0;
            o[j][2] *= a1; o[j][3] *= a1;
        }

        // ---- O += P V ----
        #pragma unroll
        for (int ks = 0; ks < 4; ks++) {
            uint32_t aph[4], apl[4];
            pack_hl(sacc[2 * ks][0],     sacc[2 * ks][1],     aph[0], apl[0]);
            pack_hl(sacc[2 * ks][2],     sacc[2 * ks][3],     aph[1], apl[1]);
            pack_hl(sacc[2 * ks + 1][0], sacc[2 * ks + 1][1], aph[2], apl[2]);
            pack_hl(sacc[2 * ks + 1][2], sacc[2 * ks + 1][3], aph[3], apl[3]);
            const int vrow = ks * 16 + ((lane >> 3) & 1) * 8 + (lane & 7);
            #pragma unroll
            for (int np = 0; np < 4; np++) {
                uint32_t vh[4], vl[4];
                uint32_t vo = SW128((uint32_t)(vrow * 128 + np * 32
                                               + (lane >> 4) * 16));
                ldsm4t(vh, s0 + 16384 + vo);
                ldsm4t(vl, s0 + 24576 + vo);
                mma16816(o[np * 2],     aph, vh[0], vh[1]);
                mma16816(o[np * 2],     aph, vl[0], vl[1]);
                mma16816(o[np * 2],     apl, vh[0], vh[1]);
                mma16816(o[np * 2 + 1], aph, vh[2], vh[3]);
                mma16816(o[np * 2 + 1], aph, vl[2], vl[3]);
                mma16816(o[np * 2 + 1], apl, vh[2], vh[3]);
            }
        }
        __syncthreads();
    }

    // ---- epilogue ----
    const float inv0 = 1.f / l0, inv1 = 1.f / l1;
    const int s0r = m0 + wm + (lane >> 2);
    const size_t r0 = (size_t)b * SEQ + s0r;
    const size_t r1 = r0 + 8;
    #pragma unroll
    for (int f = 0; f < 8; f++) {
        const int col = hd * DK + f * 8 + 2 * (lane & 3);
        uint32_t ph, pl;
        pack_hl(o[f][0] * inv0, o[f][1] * inv0, ph, pl);
        *(uint32_t*)(Ohi + r0 * EMBED + col) = ph;
        *(uint32_t*)(Olo + r0 * EMBED + col) = pl;
        pack_hl(o[f][2] * inv1, o[f][3] * inv1, ph, pl);
        *(uint32_t*)(Ohi + r1 * EMBED + col) = ph;
        *(uint32_t*)(Olo + r1 * EMBED + col) = pl;
    }
}

// ---------------------------------------------------------------------------
// Launch
// ---------------------------------------------------------------------------
extern "C" void kernel_launch(void* const* d_in, const int* in_sizes, int n_in,
                              void* d_out, int out_size)
{
    const float* x   = (const float*)d_in[0];
    const float* Wq  = (const float*)d_in[1];
    const float* bq  = (const float*)d_in[2];
    const float* Wk  = (const float*)d_in[3];
    const float* bk  = (const float*)d_in[4];
    const float* Wv  = (const float*)d_in[5];
    const float* bv  = (const float*)d_in[6];
    const float* Wo  = (const float*)d_in[7];
    const float* bo  = (const float*)d_in[8];
    const float* W1  = (const float*)d_in[9];
    const float* b1  = (const float*)d_in[10];
    const float* W2  = (const float*)d_in[11];
    const float* b2  = (const float*)d_in[12];
    const float* g1  = (const float*)d_in[13];
    const float* be1 = (const float*)d_in[14];
    const float* g2  = (const float*)d_in[15];
    const float* be2 = (const float*)d_in[16];
    float* out = (float*)d_out;

    __nv_bfloat16 *h_hi, *h_lo, *q_hi, *q_lo, *k_hi, *k_lo, *v_hi, *v_lo;
    __nv_bfloat16 *ao_hi, *ao_lo, *h2_hi, *h2_lo, *f_hi, *f_lo;
    __nv_bfloat16 *wq_hi, *wq_lo, *wk_hi, *wk_lo, *wv_hi, *wv_lo, *wo_hi, *wo_lo;
    __nv_bfloat16 *w1_hi, *w1_lo, *w2_hi, *w2_lo;
    float *x1;
    cudaGetSymbolAddress((void**)&h_hi,  g_h_hi);
    cudaGetSymbolAddress((void**)&h_lo,  g_h_lo);
    cudaGetSymbolAddress((void**)&q_hi,  g_q_hi);
    cudaGetSymbolAddress((void**)&q_lo,  g_q_lo);
    cudaGetSymbolAddress((void**)&k_hi,  g_k_hi);
    cudaGetSymbolAddress((void**)&k_lo,  g_k_lo);
    cudaGetSymbolAddress((void**)&v_hi,  g_v_hi);
    cudaGetSymbolAddress((void**)&v_lo,  g_v_lo);
    cudaGetSymbolAddress((void**)&ao_hi, g_ao_hi);
    cudaGetSymbolAddress((void**)&ao_lo, g_ao_lo);
    cudaGetSymbolAddress((void**)&x1,    g_x1);
    cudaGetSymbolAddress((void**)&h2_hi, g_h2_hi);
    cudaGetSymbolAddress((void**)&h2_lo, g_h2_lo);
    cudaGetSymbolAddress((void**)&f_hi,  g_f_hi);
    cudaGetSymbolAddress((void**)&f_lo,  g_f_lo);
    cudaGetSymbolAddress((void**)&wq_hi, g_wq_hi);
    cudaGetSymbolAddress((void**)&wq_lo, g_wq_lo);
    cudaGetSymbolAddress((void**)&wk_hi, g_wk_hi);
    cudaGetSymbolAddress((void**)&wk_lo, g_wk_lo);
    cudaGetSymbolAddress((void**)&wv_hi, g_wv_hi);
    cudaGetSymbolAddress((void**)&wv_lo, g_wv_lo);
    cudaGetSymbolAddress((void**)&wo_hi, g_wo_hi);
    cudaGetSymbolAddress((void**)&wo_lo, g_wo_lo);
    cudaGetSymbolAddress((void**)&w1_hi, g_w1_hi);
    cudaGetSymbolAddress((void**)&w1_lo, g_w1_lo);
    cudaGetSymbolAddress((void**)&w2_hi, g_w2_hi);
    cudaGetSymbolAddress((void**)&w2_lo, g_w2_lo);

    cudaFuncSetAttribute(gemm_mma<0>, cudaFuncAttributeMaxDynamicSharedMemorySize, SMEM_G);
    cudaFuncSetAttribute(gemm_mma<2>, cudaFuncAttributeMaxDynamicSharedMemorySize, SMEM_G);
    cudaFuncSetAttribute(gemm_mma<5>, cudaFuncAttributeMaxDynamicSharedMemorySize, SMEM_G);
    cudaFuncSetAttribute(gemm_mma<6>, cudaFuncAttributeMaxDynamicSharedMemorySize, SMEM_G);
    cudaFuncSetAttribute(attn_mma, cudaFuncAttributeMaxDynamicSharedMemorySize, SMEM_A);

    const int NE = EMBED * EMBED;      // 1M
    const int NF = FFN * EMBED;        // 4M
    cvt_kernel<<<NE / 1024, 256>>>(Wq, wq_hi, wq_lo, NE / 4);
    cvt_kernel<<<NE / 1024, 256>>>(Wk, wk_hi, wk_lo, NE / 4);
    cvt_kernel<<<NE / 1024, 256>>>(Wv, wv_hi, wv_lo, NE / 4);
    cvt_kernel<<<NE / 1024, 256>>>(Wo, wo_hi, wo_lo, NE / 4);
    cvt_kernel<<<NF / 1024, 256>>>(W1, w1_hi, w1_lo, NF / 4);
    cvt_kernel<<<NF / 1024, 256>>>(W2, w2_hi, w2_lo, NF / 4);

    // LN1 -> (hi, lo)
    ln_kernel<<<MROWS, 256>>>(x, g1, be1, h_hi, h_lo);

    // Q, K, V projections -> head-layout (hi, lo)
    {
        dim3 grid(EMBED / CTN, MROWS / CTM);
        gemm_mma<6><<<grid, 256, SMEM_G>>>(h_hi, h_lo, wq_hi, wq_lo, bq, nullptr,
                                           nullptr, q_hi, q_lo, MROWS, EMBED, EMBED);
        gemm_mma<6><<<grid, 256, SMEM_G>>>(h_hi, h_lo, wk_hi, wk_lo, bk, nullptr,
                                           nullptr, k_hi, k_lo, MROWS, EMBED, EMBED);
        gemm_mma<6><<<grid, 256, SMEM_G>>>(h_hi, h_lo, wv_hi, wv_lo, bv, nullptr,
                                           nullptr, v_hi, v_lo, MROWS, EMBED, EMBED);
    }

    // Attention -> ao (hi, lo)
    {
        dim3 grid(SEQ / 128, HEADS, BATCH);
        attn_mma<<<grid, 256, SMEM_A>>>(q_hi, q_lo, k_hi, k_lo, v_hi, v_lo,
                                        ao_hi, ao_lo);
    }

    // O projection + residual: x1 = x + ao @ Wo^T + bo
    {
        dim3 grid(EMBED / CTN, MROWS / CTM);
        gemm_mma<2><<<grid, 256, SMEM_G>>>(ao_hi, ao_lo, wo_hi, wo_lo, bo, x,
                                           x1, nullptr, nullptr, MROWS, EMBED, EMBED);
    }

    // LN2 -> (hi, lo)
    ln_kernel<<<MROWS, 256>>>(x1, g2, be2, h2_hi, h2_lo);

    // FFN1 + relu -> f (hi, lo)
    {
        dim3 grid(FFN / CTN, MROWS / CTM);
        gemm_mma<5><<<grid, 256, SMEM_G>>>(h2_hi, h2_lo, w1_hi, w1_lo, b1, nullptr,
                                           nullptr, f_hi, f_lo, MROWS, FFN, EMBED);
    }

    // FFN2 + residual -> out
    {
        dim3 grid(EMBED / CTN, MROWS / CTM);
        gemm_mma<2><<<grid, 256, SMEM_G>>>(f_hi, f_lo, w2_hi, w2_lo, b2, x1,
                                           out, nullptr, nullptr, MROWS, EMBED, FFN);
    }
}